// round 14
// baseline (speedup 1.0000x reference)
#include <cuda_runtime.h>

#define T_BINS 151
#define TR     32           // tile rows (i-side)
#define TC     16           // tile cols (j-side)
#define PADW   132          // 128 + 4 floats pad: float4-aligned, bank step 4
#define NREP   4            // shared histogram replicas

// Global accumulators: [0..150] pos, [151..301] neg, [302] pos count.
// Zero at module load; LAST block re-zeroes after computing the loss.
__device__ float        g_hist[2 * T_BINS + 1];
__device__ unsigned int g_done;

// Packed dual-fp32 FMA (sm_103a FFMA2; only reachable via PTX).
__device__ __forceinline__ void fma2(unsigned long long& d,
                                     unsigned long long a,
                                     unsigned long long b)
{
    asm("fma.rn.f32x2 %0, %1, %2, %3;" : "=l"(d) : "l"(a), "l"(b), "l"(d));
}

__device__ __forceinline__ float unpack_sum(unsigned long long x)
{
    float lo = __uint_as_float((unsigned int)x);
    float hi = __uint_as_float((unsigned int)(x >> 32));
    return lo + hi;
}

__global__ __launch_bounds__(256, 7) void hist_loss_kernel(
    const float* __restrict__ feats, const int* __restrict__ cls,
    float* __restrict__ out, int N, int NTC, int nblocks)
{
    extern __shared__ float sm[];
    float* As    = sm;                          // TR x PADW
    float* Bs    = As + TR * PADW;              // TC x PADW
    float* rhist = Bs + TC * PADW;              // 2*T_BINS*NREP
    int*   clsA  = (int*)(rhist + 2 * T_BINS * NREP);  // TR
    int*   clsB  = clsA + TR;                   // TC
    int*   sPos  = clsB + TC;                   // 1

    __shared__ float c1t[T_BINS];   // (t_lo[j]+step)*inv_step
    __shared__ float c2t[T_BINS];   // (step - t_hi[j])*inv_step
    __shared__ int   allow[T_BINS];
    __shared__ unsigned int s_ticket;

    const int tid = threadIdx.x;
    const float step     = (float)(2.0 / 150.0);
    const float inv_step = __fdiv_rn(1.0f, step);

    // Decode block id -> (bi, bjc): row-tile bi (32 rows), col-tile bjc (16
    // cols), only tiles with bjc >= 2*bi (right of / crossing the diagonal).
    int k = blockIdx.x, bi = 0;
    while (k >= NTC - 2 * bi) { k -= NTC - 2 * bi; ++bi; }
    const int bjc = 2 * bi + k;
    const bool cross = (bjc - 2 * bi) < 2;      // tile crosses the diagonal

    for (int i = tid; i < 2 * T_BINS * NREP; i += 256) rhist[i] = 0.0f;
    if (tid == 0) *sPos = 0;
    if (tid < TR) {
        int gi = bi * TR + tid;
        clsA[tid] = (gi < N) ? cls[gi] : -1;
    }
    if (tid < TC) {
        int gj = bjc * TC + tid;
        clsB[tid] = (gj < N) ? cls[gj] : -2;
    }
    if (tid < T_BINS) {
        float qf = (float)tid;
        float d  = __fsub_rn(__fmul_rn(qf, step), 1.0f);                   // t_lo
        float t1 = __fadd_rn(-1.0f, __fmul_rn(__fadd_rn(qf, 1.0f), step)); // t_hi
        c1t[tid]   = (d + step) * inv_step;
        c2t[tid]   = (step - t1) * inv_step;
        allow[tid] = (d == __fsub_rn(t1, step));
    }

    // Load feature tiles (A: 32x128, B: 16x128) as float4, coalesced.
    const float4* f4 = (const float4*)feats;
    for (int idx = tid; idx < TR * 32; idx += 256) {
        int r = idx >> 5, c = idx & 31;
        int gi = bi * TR + r;
        float4 va = (gi < N) ? f4[gi * 32 + c] : make_float4(0.f, 0.f, 0.f, 0.f);
        *(float4*)(As + r * PADW + c * 4) = va;
    }
    for (int idx = tid; idx < TC * 32; idx += 256) {
        int r = idx >> 5, c = idx & 31;
        int gj = bjc * TC + r;
        float4 vb = (gj < N) ? f4[gj * 32 + c] : make_float4(0.f, 0.f, 0.f, 0.f);
        *(float4*)(Bs + r * PADW + c * 4) = vb;
    }
    __syncthreads();

    // Warp w covers rows [4w, 4w+4); lanes 4x8 (row=lane>>3, col=lane&7);
    // thread: 1 row x 2 cols {c0, c0+8}. Per k4-step per warp:
    //   a: 4 rows x 16B = 1 wf; b0/b1: 8 cols broadcast = 1 wf each -> 3 wf.
    const int w    = tid >> 5;
    const int lane = tid & 31;
    const int r0 = (w << 2) + (lane >> 3);      // 0..31
    const int c0 = lane & 7;                    // 0..7 (sibling +8)

    unsigned long long acc0 = 0ull, acc1 = 0ull;
#pragma unroll 4
    for (int kk = 0; kk < 128; kk += 4) {
        ulonglong2 a  = *(const ulonglong2*)(As + r0 * PADW + kk);
        ulonglong2 b0 = *(const ulonglong2*)(Bs + c0 * PADW + kk);
        ulonglong2 b1 = *(const ulonglong2*)(Bs + (c0 + 8) * PADW + kk);
        fma2(acc0, a.x, b0.x); fma2(acc0, a.y, b0.y);
        fma2(acc1, a.x, b1.x); fma2(acc1, a.y, b1.y);
    }

    // ---- Binning (reference fp32 semantics; weights via 1-FMA tables) ----
    const int rep = tid & (NREP - 1);
    const int ca  = clsA[r0];
    const int gi  = bi * TR + r0;
    unsigned long long accs[2] = { acc0, acc1 };
    int localPos = 0;
#pragma unroll
    for (int v = 0; v < 2; ++v) {
        int rj = c0 + 8 * v;
        int gj = bjc * TC + rj;
        if ((!cross || gi < gj) && gj < N) {
            float s  = unpack_sum(accs[v]);
            float qf = floorf(fmaf(s, inv_step, inv_step));  // (s+1)/step
            int   j0 = (int)qf;
            int   ng = (ca == clsB[rj]) ? 0 : 1;
            localPos += (ng == 0);
            if (j0 >= 0 && j0 < T_BINS) {
                float wb = fmaf(-s, inv_step, c1t[j0]);
                atomicAdd(&rhist[(j0 * 2 + ng) * NREP + rep], wb);
                if (allow[j0] && j0 + 1 < T_BINS) {
                    float wa = fmaf(s, inv_step, c2t[j0]);
                    atomicAdd(&rhist[((j0 + 1) * 2 + ng) * NREP + rep], wa);
                }
            }
        }
    }
    int warpPos = __reduce_add_sync(0xFFFFFFFFu, localPos);
    if (lane == 0 && warpPos) atomicAdd(sPos, warpPos);
    __syncthreads();

    // Merge replicas and flush into the global accumulator (L2 atomics).
    for (int i = tid; i < 2 * T_BINS; i += 256) {
        int bin = (i < T_BINS) ? i : (i - T_BINS);
        int ng  = (i < T_BINS) ? 0 : 1;
        const float* src = &rhist[(bin * 2 + ng) * NREP];
        float v = src[0] + src[1] + src[2] + src[3];
        if (v != 0.0f) atomicAdd(&g_hist[i], v);
    }
    if (tid == 0 && *sPos) atomicAdd(&g_hist[2 * T_BINS], (float)(*sPos));

    // ---- last-block-done finalize ----
    __threadfence();
    if (tid == 0) s_ticket = atomicInc(&g_done, 0xFFFFFFFFu);
    __syncthreads();
    if (s_ticket != (unsigned)(nblocks - 1)) return;
    __threadfence();

    float* hp  = rhist;             // reuse shared memory
    float* hn  = rhist + T_BINS;
    float* red = As;                // 256 floats
    __shared__ float s_inv_pos, s_inv_neg;

    float vp = 0.f, vn = 0.f;
    if (tid < T_BINS) {
        vp = __ldcg(&g_hist[tid]);
        vn = __ldcg(&g_hist[T_BINS + tid]);
    }
    if (tid == 0) {
        float cnt  = __ldcg(&g_hist[2 * T_BINS]);
        float Ptot = 0.5f * (float)N * (float)(N - 1);
        s_inv_pos = 1.0f / cnt;
        s_inv_neg = 1.0f / (Ptot - cnt);
    }
    __syncthreads();
    if (tid < T_BINS) {
        hp[tid] = vp * s_inv_pos;
        hn[tid] = vn * s_inv_neg;
    }
    __syncthreads();

    // inclusive scan of hp (Hillis-Steele, 8 steps)
    for (int off = 1; off < T_BINS; off <<= 1) {
        float v = (tid < T_BINS && tid >= off) ? hp[tid - off] : 0.f;
        __syncthreads();
        if (tid < T_BINS) hp[tid] += v;
        __syncthreads();
    }

    // dot(hn, cdf) via power-of-2 tree reduce
    red[tid] = (tid < T_BINS) ? hn[tid] * hp[tid] : 0.f;
    __syncthreads();
#pragma unroll
    for (int s = 128; s > 0; s >>= 1) {
        if (tid < s) red[tid] += red[tid + s];
        __syncthreads();
    }
    if (tid == 0) out[0] = red[0];

    // Reset globals for the next replay (invariant: zero at kernel entry).
    for (int i = tid; i < 2 * T_BINS + 1; i += 256) g_hist[i] = 0.0f;
    if (tid == 0) g_done = 0u;
}

extern "C" void kernel_launch(void* const* d_in, const int* in_sizes, int n_in,
                              void* d_out, int out_size)
{
    const float* feats = (const float*)d_in[0];
    const int*   cls   = (const int*)d_in[1];
    int N   = in_sizes[1];                // classes element count = rows
    int NTR = (N + TR - 1) / TR;
    int NTC = (N + TC - 1) / TC;
    int nblocks = 0;
    for (int b = 0; b < NTR; ++b) {
        int c = NTC - 2 * b;
        if (c > 0) nblocks += c;          // 1056 for N=1024
    }

    size_t smem = (size_t)(TR * PADW + TC * PADW + 2 * T_BINS * NREP) * sizeof(float)
                + (size_t)(TR + TC + 4) * sizeof(int);
    cudaFuncSetAttribute(hist_loss_kernel,
                         cudaFuncAttributeMaxDynamicSharedMemorySize, (int)smem);

    hist_loss_kernel<<<nblocks, 256, smem>>>(feats, cls, (float*)d_out,
                                             N, NTC, nblocks);
}

// round 15
// speedup vs baseline: 1.0051x; 1.0051x over previous
#include <cuda_runtime.h>

#define T_BINS 151
#define TILE   32
#define PADW   132          // 128 + 4 floats pad: float4-aligned, bank step 4
#define NREP   8            // aggregate-table replicas (bank spread)
#define FXS    524288.0f    // 2^19 fixed-point scale for (s+1)

// Global aggregate table: slot (j*2+ng) holds {count:[40,64), sum_fx:[0,40)}.
// Exact integers -> deterministic. Zeroed by the LAST block after the loss.
__device__ unsigned long long g_aggr[2 * T_BINS];
__device__ unsigned int      g_done;

// Packed dual-fp32 FMA (sm_103a FFMA2; only reachable via PTX).
__device__ __forceinline__ void fma2(unsigned long long& d,
                                     unsigned long long a,
                                     unsigned long long b)
{
    asm("fma.rn.f32x2 %0, %1, %2, %3;" : "=l"(d) : "l"(a), "l"(b), "l"(d));
}

__device__ __forceinline__ float unpack_sum(unsigned long long x)
{
    float lo = __uint_as_float((unsigned int)x);
    float hi = __uint_as_float((unsigned int)(x >> 32));
    return lo + hi;
}

__global__ __launch_bounds__(256) void hist_loss_kernel(
    const float* __restrict__ feats, const int* __restrict__ cls,
    float* __restrict__ out, int N, int NT, int nblocks)
{
    extern __shared__ float sm[];
    float* As = sm;                                   // TILE x PADW
    float* Bs = As + TILE * PADW;                     // TILE x PADW
    unsigned long long* aggr =
        (unsigned long long*)(Bs + TILE * PADW);      // 2*T_BINS*NREP u64
    int* clsA = (int*)(aggr + 2 * T_BINS * NREP);     // TILE
    int* clsB = clsA + TILE;                          // TILE

    __shared__ unsigned int s_ticket;

    const int tid = threadIdx.x;
    const float step     = (float)(2.0 / 150.0);
    const float inv_step = __fdiv_rn(1.0f, step);

    // Decode linear block id -> upper-triangular tile (bi, bj), bi <= bj.
    int k = blockIdx.x, bi = 0;
    while (k >= NT - bi) { k -= NT - bi; ++bi; }
    const int bj = bi + k;
    const bool diag = (bi == bj);

    for (int i = tid; i < 2 * T_BINS * NREP; i += 256) aggr[i] = 0ull;
    if (tid < TILE) {
        int gi = bi * TILE + tid;
        clsA[tid] = (gi < N) ? cls[gi] : -1;
        int gj = bj * TILE + tid;
        clsB[tid] = (gj < N) ? cls[gj] : -2;
    }

    // Load both feature tiles (32 rows x 128 floats) as float4, coalesced.
    const float4* f4 = (const float4*)feats;
    for (int idx = tid; idx < TILE * 32; idx += 256) {
        int r = idx >> 5, c = idx & 31;
        int gi = bi * TILE + r;
        float4 va = (gi < N) ? f4[gi * 32 + c] : make_float4(0.f, 0.f, 0.f, 0.f);
        *(float4*)(As + r * PADW + c * 4) = va;
        int gj = bj * TILE + r;
        float4 vb = (gj < N) ? f4[gj * 32 + c] : make_float4(0.f, 0.f, 0.f, 0.f);
        *(float4*)(Bs + r * PADW + c * 4) = vb;
    }
    __syncthreads();

    // Warp-square mapping (R11 shape): warps 2x4; lanes 8x4; micro 2x2:
    // rows {r0, r0+8}, cols {c0, c0+4}.
    const int w    = tid >> 5;
    const int lane = tid & 31;
    const int r0 = ((w >> 2) << 4) + (lane >> 2);   // 0..31
    const int c0 = ((w & 3) << 3) + (lane & 3);     // 0..31

    unsigned long long acc[2][2];
#pragma unroll
    for (int u = 0; u < 2; ++u)
#pragma unroll
        for (int v = 0; v < 2; ++v) acc[u][v] = 0ull;

#pragma unroll 2
    for (int kk = 0; kk < 128; kk += 4) {
        ulonglong2 a0 = *(const ulonglong2*)(As + r0 * PADW + kk);
        ulonglong2 a1 = *(const ulonglong2*)(As + (r0 + 8) * PADW + kk);
        ulonglong2 b0 = *(const ulonglong2*)(Bs + c0 * PADW + kk);
        ulonglong2 b1 = *(const ulonglong2*)(Bs + (c0 + 4) * PADW + kk);
        fma2(acc[0][0], a0.x, b0.x); fma2(acc[0][0], a0.y, b0.y);
        fma2(acc[0][1], a0.x, b1.x); fma2(acc[0][1], a0.y, b1.y);
        fma2(acc[1][0], a1.x, b0.x); fma2(acc[1][0], a1.y, b0.y);
        fma2(acc[1][1], a1.x, b1.x); fma2(acc[1][1], a1.y, b1.y);
    }

    // ---- Binning: ONE u64 atomic per pair. Bin index is the exact fp32
    // floor((s+1)/step) path (reference semantics); weights reconstructed in
    // the finalize from (count, sum) -- they are linear in s per bin.
    const int rep = tid & (NREP - 1);
    const int ca[2] = { clsA[r0], clsA[r0 + 8] };
    const int cb[2] = { clsB[c0], clsB[c0 + 4] };
#pragma unroll
    for (int u = 0; u < 2; ++u) {
#pragma unroll
        for (int v = 0; v < 2; ++v) {
            int ri = r0 + 8 * u, rj = c0 + 4 * v;
            if ((!diag || ri < rj) && (bj * TILE + rj) < N) {
                float s  = unpack_sum(acc[u][v]);
                float qf = floorf(fmaf(s, inv_step, inv_step));  // (s+1)/step
                int   j0 = (int)qf;
                int   ng = (ca[u] == cb[v]) ? 0 : 1;
                if (j0 >= 0 && j0 < T_BINS) {
                    unsigned int fx = __float2uint_rn(fmaf(s, FXS, FXS));
                    atomicAdd(&aggr[(j0 * 2 + ng) * NREP + rep],
                              (1ull << 40) + (unsigned long long)fx);
                }
            }
        }
    }
    __syncthreads();

    // Merge replicas; exact integer REDG.64 into the global table.
    for (int i = tid; i < 2 * T_BINS; i += 256) {
        const unsigned long long* src = &aggr[i * NREP];
        unsigned long long v = 0ull;
#pragma unroll
        for (int r = 0; r < NREP; ++r) v += src[r];
        if (v) atomicAdd(&g_aggr[i], v);
    }

    // ---- last-block-done finalize ----
    __threadfence();
    if (tid == 0) s_ticket = atomicInc(&g_done, 0xFFFFFFFFu);
    __syncthreads();
    if (s_ticket != (unsigned)(nblocks - 1)) return;
    __threadfence();

    // Per-bin reconstruction (reference fp32 edge semantics):
    //   hist[ng][j] = c1[j]*n_j - ssum_j*inv
    //               + (j>0 && allow[j-1]) * (ssum_{j-1}*inv + c2[j-1]*n_{j-1})
    __shared__ float s_np[T_BINS], s_sp[T_BINS], s_nn[T_BINS], s_sn[T_BINS];
    __shared__ float s_c1[T_BINS], s_c2[T_BINS];
    __shared__ int   s_al[T_BINS];
    __shared__ float s_inv_pos, s_inv_neg;
    float* hp  = As;                 // reuse tile smem
    float* hn  = As + T_BINS;
    float* red = Bs;                 // 256 floats

    if (tid < T_BINS) {
        float qf = (float)tid;
        float d  = __fsub_rn(__fmul_rn(qf, step), 1.0f);                   // t_lo
        float t1 = __fadd_rn(-1.0f, __fmul_rn(__fadd_rn(qf, 1.0f), step)); // t_hi
        s_c1[tid] = (d + step) * inv_step;
        s_c2[tid] = (step - t1) * inv_step;
        s_al[tid] = (d == __fsub_rn(t1, step));

        unsigned long long vp = __ldcg(&g_aggr[tid * 2 + 0]);
        unsigned long long vn = __ldcg(&g_aggr[tid * 2 + 1]);
        double npd = (double)(vp >> 40);
        double nnd = (double)(vn >> 40);
        const double MSK = (double)((1ull << 40) - 1);  // unused; fields via &
        (void)MSK;
        double spd = (double)(vp & ((1ull << 40) - 1)) * (1.0 / 524288.0) - npd;
        double snd = (double)(vn & ((1ull << 40) - 1)) * (1.0 / 524288.0) - nnd;
        s_np[tid] = (float)npd;  s_sp[tid] = (float)spd;
        s_nn[tid] = (float)nnd;  s_sn[tid] = (float)snd;
    }
    // posSize = sum of pos counts
    {
        float c = (tid < T_BINS) ? (float)(__ldcg(&g_aggr[tid * 2]) >> 40) : 0.f;
        red[tid] = c;
        __syncthreads();
#pragma unroll
        for (int s2 = 128; s2 > 0; s2 >>= 1) {
            if (tid < s2) red[tid] += red[tid + s2];
            __syncthreads();
        }
        if (tid == 0) {
            float cnt  = red[0];
            float Ptot = 0.5f * (float)N * (float)(N - 1);
            s_inv_pos = 1.0f / cnt;
            s_inv_neg = 1.0f / (Ptot - cnt);
        }
        __syncthreads();
    }

    if (tid < T_BINS) {
        float bp = s_c1[tid] * s_np[tid] - s_sp[tid] * inv_step;
        float bn = s_c1[tid] * s_nn[tid] - s_sn[tid] * inv_step;
        if (tid > 0 && s_al[tid - 1]) {
            bp += s_sp[tid - 1] * inv_step + s_c2[tid - 1] * s_np[tid - 1];
            bn += s_sn[tid - 1] * inv_step + s_c2[tid - 1] * s_nn[tid - 1];
        }
        hp[tid] = bp * s_inv_pos;
        hn[tid] = bn * s_inv_neg;
    }
    __syncthreads();

    // inclusive scan of hp (Hillis-Steele, 8 steps)
    for (int off = 1; off < T_BINS; off <<= 1) {
        float v = (tid < T_BINS && tid >= off) ? hp[tid - off] : 0.f;
        __syncthreads();
        if (tid < T_BINS) hp[tid] += v;
        __syncthreads();
    }

    // dot(hn, cdf) via power-of-2 tree reduce
    red[tid] = (tid < T_BINS) ? hn[tid] * hp[tid] : 0.f;
    __syncthreads();
#pragma unroll
    for (int s2 = 128; s2 > 0; s2 >>= 1) {
        if (tid < s2) red[tid] += red[tid + s2];
        __syncthreads();
    }
    if (tid == 0) out[0] = red[0];

    // Reset globals for the next replay (invariant: zero at kernel entry).
    for (int i = tid; i < 2 * T_BINS; i += 256) g_aggr[i] = 0ull;
    if (tid == 0) g_done = 0u;
}

extern "C" void kernel_launch(void* const* d_in, const int* in_sizes, int n_in,
                              void* d_out, int out_size)
{
    const float* feats = (const float*)d_in[0];
    const int*   cls   = (const int*)d_in[1];
    int N  = in_sizes[1];                 // classes element count = rows
    int NT = (N + TILE - 1) / TILE;
    int nblocks = NT * (NT + 1) / 2;      // 528 for N=1024

    size_t smem = (size_t)(2 * TILE * PADW) * sizeof(float)
                + (size_t)(2 * T_BINS * NREP) * sizeof(unsigned long long)
                + (size_t)(2 * TILE + 4) * sizeof(int);
    cudaFuncSetAttribute(hist_loss_kernel,
                         cudaFuncAttributeMaxDynamicSharedMemorySize, (int)smem);

    hist_loss_kernel<<<nblocks, 256, smem>>>(feats, cls, (float*)d_out,
                                             N, NT, nblocks);
}

// round 16
// speedup vs baseline: 1.0957x; 1.0902x over previous
#include <cuda_runtime.h>

#define T_BINS 151
#define TILE   32
#define PADW   132          // 128 + 4 floats pad: float4-aligned, bank step 4
#define NREP   16           // u32 aggregate replicas (bank spread)
#define FXS    262144.0f    // 2^18 fixed-point scale for (s+1)
#define FXMASK ((1u << 25) - 1u)

// Global aggregate table: slot (j*2+ng) = {count:[40,64), sum_fx:[0,40)}.
// Exact integers -> deterministic. Zeroed by the LAST block after the loss.
__device__ unsigned long long g_aggr[2 * T_BINS];
__device__ unsigned int      g_done;

// Packed dual-fp32 FMA (sm_103a FFMA2; only reachable via PTX).
__device__ __forceinline__ void fma2(unsigned long long& d,
                                     unsigned long long a,
                                     unsigned long long b)
{
    asm("fma.rn.f32x2 %0, %1, %2, %3;" : "=l"(d) : "l"(a), "l"(b), "l"(d));
}

__device__ __forceinline__ float unpack_sum(unsigned long long x)
{
    float lo = __uint_as_float((unsigned int)x);
    float hi = __uint_as_float((unsigned int)(x >> 32));
    return lo + hi;
}

__global__ __launch_bounds__(256) void hist_loss_kernel(
    const float* __restrict__ feats, const int* __restrict__ cls,
    float* __restrict__ out, int N, int NT, int nblocks)
{
    extern __shared__ float sm[];
    float* As = sm;                                   // TILE x PADW
    float* Bs = As + TILE * PADW;                     // TILE x PADW
    unsigned int* aggr = (unsigned int*)(Bs + TILE * PADW); // 2*T_BINS*NREP
    int* clsA = (int*)(aggr + 2 * T_BINS * NREP);     // TILE
    int* clsB = clsA + TILE;                          // TILE

    __shared__ unsigned int s_ticket;

    const int tid = threadIdx.x;
    const float step     = (float)(2.0 / 150.0);
    const float inv_step = __fdiv_rn(1.0f, step);

    // Decode linear block id -> upper-triangular tile (bi, bj), bi <= bj.
    int k = blockIdx.x, bi = 0;
    while (k >= NT - bi) { k -= NT - bi; ++bi; }
    const int bj = bi + k;
    const bool diag = (bi == bj);

    for (int i = tid; i < 2 * T_BINS * NREP; i += 256) aggr[i] = 0u;
    if (tid < TILE) {
        int gi = bi * TILE + tid;
        clsA[tid] = (gi < N) ? cls[gi] : -1;
        int gj = bj * TILE + tid;
        clsB[tid] = (gj < N) ? cls[gj] : -2;
    }

    // Load both feature tiles (32 rows x 128 floats) as float4, coalesced.
    const float4* f4 = (const float4*)feats;
    for (int idx = tid; idx < TILE * 32; idx += 256) {
        int r = idx >> 5, c = idx & 31;
        int gi = bi * TILE + r;
        float4 va = (gi < N) ? f4[gi * 32 + c] : make_float4(0.f, 0.f, 0.f, 0.f);
        *(float4*)(As + r * PADW + c * 4) = va;
        int gj = bj * TILE + r;
        float4 vb = (gj < N) ? f4[gj * 32 + c] : make_float4(0.f, 0.f, 0.f, 0.f);
        *(float4*)(Bs + r * PADW + c * 4) = vb;
    }
    __syncthreads();

    // Warp-square mapping (R11 shape): warps 2x4; lanes 8x4; micro 2x2:
    // rows {r0, r0+8}, cols {c0, c0+4}.
    const int w    = tid >> 5;
    const int lane = tid & 31;
    const int r0 = ((w >> 2) << 4) + (lane >> 2);   // 0..31
    const int c0 = ((w & 3) << 3) + (lane & 3);     // 0..31

    unsigned long long acc[2][2];
#pragma unroll
    for (int u = 0; u < 2; ++u)
#pragma unroll
        for (int v = 0; v < 2; ++v) acc[u][v] = 0ull;

#pragma unroll 2
    for (int kk = 0; kk < 128; kk += 4) {
        ulonglong2 a0 = *(const ulonglong2*)(As + r0 * PADW + kk);
        ulonglong2 a1 = *(const ulonglong2*)(As + (r0 + 8) * PADW + kk);
        ulonglong2 b0 = *(const ulonglong2*)(Bs + c0 * PADW + kk);
        ulonglong2 b1 = *(const ulonglong2*)(Bs + (c0 + 4) * PADW + kk);
        fma2(acc[0][0], a0.x, b0.x); fma2(acc[0][0], a0.y, b0.y);
        fma2(acc[0][1], a0.x, b1.x); fma2(acc[0][1], a0.y, b1.y);
        fma2(acc[1][0], a1.x, b0.x); fma2(acc[1][0], a1.y, b0.y);
        fma2(acc[1][1], a1.x, b1.x); fma2(acc[1][1], a1.y, b1.y);
    }

    // ---- Binning: ONE u32 shared atomic per pair.
    // Slot packs {count:[25,32), fx=(s+1)*2^18:[0,25)}. Per-slot bounds:
    // <=16 same-rep threads x 4 pairs = 64 counts (7 bits ok); sum_fx <=
    // 64*2^19 < 2^25 (no field overflow). Weights are linear in s per bin,
    // reconstructed exactly in the finalize (incl. the reference's bitwise
    // allow[] edge gate). Bin index keeps the reference fp32 floor path.
    const int rep = tid & (NREP - 1);
    const int ca[2] = { clsA[r0], clsA[r0 + 8] };
    const int cb[2] = { clsB[c0], clsB[c0 + 4] };
#pragma unroll
    for (int u = 0; u < 2; ++u) {
#pragma unroll
        for (int v = 0; v < 2; ++v) {
            int ri = r0 + 8 * u, rj = c0 + 4 * v;
            if ((!diag || ri < rj) && (bj * TILE + rj) < N) {
                float s  = unpack_sum(acc[u][v]);
                float qf = floorf(fmaf(s, inv_step, inv_step));  // (s+1)/step
                int   j0 = (int)qf;
                int   ng = (ca[u] == cb[v]) ? 0 : 1;
                if (j0 >= 0 && j0 < T_BINS) {
                    unsigned int fx = __float2uint_rn(fmaf(s, FXS, FXS));
                    atomicAdd(&aggr[(j0 * 2 + ng) * NREP + rep],
                              (1u << 25) + fx);
                }
            }
        }
    }
    __syncthreads();

    // Merge replicas (split fields -> no overflow), one u64 REDG per slot.
    for (int i = tid; i < 2 * T_BINS; i += 256) {
        const unsigned int* src = &aggr[i * NREP];
        unsigned long long cnt = 0ull, fxs = 0ull;
#pragma unroll
        for (int r = 0; r < NREP; ++r) {
            unsigned int v = src[r];
            cnt += v >> 25;
            fxs += v & FXMASK;
        }
        if (cnt) atomicAdd(&g_aggr[i], (cnt << 40) + fxs);
    }

    // ---- last-block-done finalize ----
    __threadfence();
    if (tid == 0) s_ticket = atomicInc(&g_done, 0xFFFFFFFFu);
    __syncthreads();
    if (s_ticket != (unsigned)(nblocks - 1)) return;
    __threadfence();

    // Per-bin reconstruction (reference fp32 edge semantics):
    //   hist[ng][j] = c1[j]*n_j - ssum_j*inv_step
    //               + (j>0 && allow[j-1])*(ssum_{j-1}*inv_step + c2[j-1]*n_{j-1})
    __shared__ float s_np[T_BINS], s_sp[T_BINS], s_nn[T_BINS], s_sn[T_BINS];
    __shared__ float s_c1[T_BINS], s_c2[T_BINS];
    __shared__ int   s_al[T_BINS];
    __shared__ float s_inv_pos, s_inv_neg;
    float* hp  = As;                 // reuse tile smem
    float* hn  = As + T_BINS;
    float* red = Bs;                 // 256 floats

    if (tid < T_BINS) {
        float qf = (float)tid;
        float d  = __fsub_rn(__fmul_rn(qf, step), 1.0f);                   // t_lo
        float t1 = __fadd_rn(-1.0f, __fmul_rn(__fadd_rn(qf, 1.0f), step)); // t_hi
        s_c1[tid] = (d + step) * inv_step;
        s_c2[tid] = (step - t1) * inv_step;
        s_al[tid] = (d == __fsub_rn(t1, step));

        unsigned long long vp = __ldcg(&g_aggr[tid * 2 + 0]);
        unsigned long long vn = __ldcg(&g_aggr[tid * 2 + 1]);
        double npd = (double)(vp >> 40);
        double nnd = (double)(vn >> 40);
        double spd = (double)(vp & ((1ull << 40) - 1)) * (1.0 / 262144.0) - npd;
        double snd = (double)(vn & ((1ull << 40) - 1)) * (1.0 / 262144.0) - nnd;
        s_np[tid] = (float)npd;  s_sp[tid] = (float)spd;
        s_nn[tid] = (float)nnd;  s_sn[tid] = (float)snd;
    }
    // posSize = sum of pos counts
    {
        float c = (tid < T_BINS) ? (float)(__ldcg(&g_aggr[tid * 2]) >> 40) : 0.f;
        red[tid] = c;
        __syncthreads();
#pragma unroll
        for (int s2 = 128; s2 > 0; s2 >>= 1) {
            if (tid < s2) red[tid] += red[tid + s2];
            __syncthreads();
        }
        if (tid == 0) {
            float cnt  = red[0];
            float Ptot = 0.5f * (float)N * (float)(N - 1);
            s_inv_pos = 1.0f / cnt;
            s_inv_neg = 1.0f / (Ptot - cnt);
        }
        __syncthreads();
    }

    if (tid < T_BINS) {
        float bp = s_c1[tid] * s_np[tid] - s_sp[tid] * inv_step;
        float bn = s_c1[tid] * s_nn[tid] - s_sn[tid] * inv_step;
        if (tid > 0 && s_al[tid - 1]) {
            bp += s_sp[tid - 1] * inv_step + s_c2[tid - 1] * s_np[tid - 1];
            bn += s_sn[tid - 1] * inv_step + s_c2[tid - 1] * s_nn[tid - 1];
        }
        hp[tid] = bp * s_inv_pos;
        hn[tid] = bn * s_inv_neg;
    }
    __syncthreads();

    // inclusive scan of hp (Hillis-Steele, 8 steps)
    for (int off = 1; off < T_BINS; off <<= 1) {
        float v = (tid < T_BINS && tid >= off) ? hp[tid - off] : 0.f;
        __syncthreads();
        if (tid < T_BINS) hp[tid] += v;
        __syncthreads();
    }

    // dot(hn, cdf) via power-of-2 tree reduce
    red[tid] = (tid < T_BINS) ? hn[tid] * hp[tid] : 0.f;
    __syncthreads();
#pragma unroll
    for (int s2 = 128; s2 > 0; s2 >>= 1) {
        if (tid < s2) red[tid] += red[tid + s2];
        __syncthreads();
    }
    if (tid == 0) out[0] = red[0];

    // Reset globals for the next replay (invariant: zero at kernel entry).
    for (int i = tid; i < 2 * T_BINS; i += 256) g_aggr[i] = 0ull;
    if (tid == 0) g_done = 0u;
}

extern "C" void kernel_launch(void* const* d_in, const int* in_sizes, int n_in,
                              void* d_out, int out_size)
{
    const float* feats = (const float*)d_in[0];
    const int*   cls   = (const int*)d_in[1];
    int N  = in_sizes[1];                 // classes element count = rows
    int NT = (N + TILE - 1) / TILE;
    int nblocks = NT * (NT + 1) / 2;      // 528 for N=1024

    size_t smem = (size_t)(2 * TILE * PADW) * sizeof(float)
                + (size_t)(2 * T_BINS * NREP) * sizeof(unsigned int)
                + (size_t)(2 * TILE + 4) * sizeof(int);
    cudaFuncSetAttribute(hist_loss_kernel,
                         cudaFuncAttributeMaxDynamicSharedMemorySize, (int)smem);

    hist_loss_kernel<<<nblocks, 256, smem>>>(feats, cls, (float*)d_out,
                                             N, NT, nblocks);
}

// round 17
// speedup vs baseline: 1.3189x; 1.2037x over previous
#include <cuda_runtime.h>

#define T_BINS 151
#define TILE   32
#define PADW   132          // 128 + 4 floats pad: float4-aligned, bank step 4
#define NREP   8            // u32 aggregate replicas (bank spread)
#define FXS    65536.0f     // 2^16 fixed-point scale for (s+1)
#define FXCAP  ((1u << 17) - 1u)   // clamp: 128 * FXCAP < 2^24 (no overflow)
#define FXMASK ((1u << 24) - 1u)

// Global aggregate table: slot (j*2+ng) = {count:[40,64), sum_fx:[0,40)}.
// Exact integers -> deterministic. Zeroed by the LAST block after the loss.
__device__ unsigned long long g_aggr[2 * T_BINS];
__device__ unsigned int      g_done;

// Packed dual-fp32 FMA (sm_103a FFMA2; only reachable via PTX).
__device__ __forceinline__ void fma2(unsigned long long& d,
                                     unsigned long long a,
                                     unsigned long long b)
{
    asm("fma.rn.f32x2 %0, %1, %2, %3;" : "=l"(d) : "l"(a), "l"(b), "l"(d));
}

__device__ __forceinline__ float unpack_sum(unsigned long long x)
{
    float lo = __uint_as_float((unsigned int)x);
    float hi = __uint_as_float((unsigned int)(x >> 32));
    return lo + hi;
}

__global__ __launch_bounds__(256) void hist_loss_kernel(
    const float* __restrict__ feats, const int* __restrict__ cls,
    float* __restrict__ out, int N, int NT, int nblocks)
{
    extern __shared__ float sm[];
    float* As = sm;                                   // TILE x PADW
    float* Bs = As + TILE * PADW;                     // TILE x PADW
    unsigned int* aggr = (unsigned int*)(Bs + TILE * PADW); // 2*T_BINS*NREP
    int* clsA = (int*)(aggr + 2 * T_BINS * NREP);     // TILE
    int* clsB = clsA + TILE;                          // TILE

    __shared__ unsigned int s_ticket;

    const int tid = threadIdx.x;
    const float step     = (float)(2.0 / 150.0);
    const float inv_step = __fdiv_rn(1.0f, step);

    // Decode linear block id -> upper-triangular tile (bi, bj), bi <= bj.
    int k = blockIdx.x, bi = 0;
    while (k >= NT - bi) { k -= NT - bi; ++bi; }
    const int bj = bi + k;
    const bool diag = (bi == bj);

    for (int i = tid; i < 2 * T_BINS * NREP; i += 256) aggr[i] = 0u;
    if (tid < TILE) {
        int gi = bi * TILE + tid;
        clsA[tid] = (gi < N) ? cls[gi] : -1;
        int gj = bj * TILE + tid;
        clsB[tid] = (gj < N) ? cls[gj] : -2;
    }

    // Load both feature tiles (32 rows x 128 floats) as float4, coalesced.
    const float4* f4 = (const float4*)feats;
    for (int idx = tid; idx < TILE * 32; idx += 256) {
        int r = idx >> 5, c = idx & 31;
        int gi = bi * TILE + r;
        float4 va = (gi < N) ? f4[gi * 32 + c] : make_float4(0.f, 0.f, 0.f, 0.f);
        *(float4*)(As + r * PADW + c * 4) = va;
        int gj = bj * TILE + r;
        float4 vb = (gj < N) ? f4[gj * 32 + c] : make_float4(0.f, 0.f, 0.f, 0.f);
        *(float4*)(Bs + r * PADW + c * 4) = vb;
    }
    __syncthreads();

    // Warp-square mapping (R11 shape): warps 2x4; lanes 8x4; micro 2x2:
    // rows {r0, r0+8}, cols {c0, c0+4}.
    const int w    = tid >> 5;
    const int lane = tid & 31;
    const int r0 = ((w >> 2) << 4) + (lane >> 2);   // 0..31
    const int c0 = ((w & 3) << 3) + (lane & 3);     // 0..31

    unsigned long long acc[2][2];
#pragma unroll
    for (int u = 0; u < 2; ++u)
#pragma unroll
        for (int v = 0; v < 2; ++v) acc[u][v] = 0ull;

#pragma unroll 2
    for (int kk = 0; kk < 128; kk += 4) {
        ulonglong2 a0 = *(const ulonglong2*)(As + r0 * PADW + kk);
        ulonglong2 a1 = *(const ulonglong2*)(As + (r0 + 8) * PADW + kk);
        ulonglong2 b0 = *(const ulonglong2*)(Bs + c0 * PADW + kk);
        ulonglong2 b1 = *(const ulonglong2*)(Bs + (c0 + 4) * PADW + kk);
        fma2(acc[0][0], a0.x, b0.x); fma2(acc[0][0], a0.y, b0.y);
        fma2(acc[0][1], a0.x, b1.x); fma2(acc[0][1], a0.y, b1.y);
        fma2(acc[1][0], a1.x, b0.x); fma2(acc[1][0], a1.y, b0.y);
        fma2(acc[1][1], a1.x, b1.x); fma2(acc[1][1], a1.y, b1.y);
    }

    // ---- Binning: ONE u32 shared atomic per pair.
    // Slot packs {count:[24,32), fx=(s+1)*2^16:[0,24)}. Bounds: <=32
    // same-rep threads x 4 pairs = 128 counts (<=255 ok); fx clamped to
    // 2^17-1 -> sum_fx <= 128*(2^17-1) < 2^24 (guaranteed no overflow).
    // Weights are linear in s per bin; reconstructed in the finalize with
    // the reference's bitwise allow[] edge gate. Bin index keeps the exact
    // fp32 floor path.
    const int rep = tid & (NREP - 1);
    const int ca[2] = { clsA[r0], clsA[r0 + 8] };
    const int cb[2] = { clsB[c0], clsB[c0 + 4] };
#pragma unroll
    for (int u = 0; u < 2; ++u) {
#pragma unroll
        for (int v = 0; v < 2; ++v) {
            int ri = r0 + 8 * u, rj = c0 + 4 * v;
            if ((!diag || ri < rj) && (bj * TILE + rj) < N) {
                float s  = unpack_sum(acc[u][v]);
                float qf = floorf(fmaf(s, inv_step, inv_step));  // (s+1)/step
                int   j0 = (int)qf;
                int   ng = (ca[u] == cb[v]) ? 0 : 1;
                if (j0 >= 0 && j0 < T_BINS) {
                    unsigned int fx = __float2uint_rn(fmaf(s, FXS, FXS));
                    fx = umin(fx, FXCAP);
                    atomicAdd(&aggr[(j0 * 2 + ng) * NREP + rep],
                              (1u << 24) + fx);
                }
            }
        }
    }
    __syncthreads();

    // Merge replicas (split fields), one u64 REDG per slot (exact ints).
    for (int i = tid; i < 2 * T_BINS; i += 256) {
        const unsigned int* src = &aggr[i * NREP];
        unsigned long long cnt = 0ull, fxs = 0ull;
#pragma unroll
        for (int r = 0; r < NREP; ++r) {
            unsigned int v = src[r];
            cnt += v >> 24;
            fxs += v & FXMASK;
        }
        if (cnt) atomicAdd(&g_aggr[i], (cnt << 40) + fxs);
    }

    // ---- last-block-done finalize ----
    __threadfence();
    if (tid == 0) s_ticket = atomicInc(&g_done, 0xFFFFFFFFu);
    __syncthreads();
    if (s_ticket != (unsigned)(nblocks - 1)) return;
    __threadfence();

    // Per-bin reconstruction (reference fp32 edge semantics):
    //   hist[ng][j] = c1[j]*n_j - ssum_j*inv_step
    //               + (j>0 && allow[j-1])*(ssum_{j-1}*inv_step + c2[j-1]*n_{j-1})
    __shared__ float s_np[T_BINS], s_sp[T_BINS], s_nn[T_BINS], s_sn[T_BINS];
    __shared__ float s_c1[T_BINS], s_c2[T_BINS];
    __shared__ int   s_al[T_BINS];
    __shared__ float s_inv_pos, s_inv_neg;
    float* hp  = As;                 // reuse tile smem
    float* hn  = As + T_BINS;
    float* red = Bs;                 // 256 floats

    if (tid < T_BINS) {
        float qf = (float)tid;
        float d  = __fsub_rn(__fmul_rn(qf, step), 1.0f);                   // t_lo
        float t1 = __fadd_rn(-1.0f, __fmul_rn(__fadd_rn(qf, 1.0f), step)); // t_hi
        s_c1[tid] = (d + step) * inv_step;
        s_c2[tid] = (step - t1) * inv_step;
        s_al[tid] = (d == __fsub_rn(t1, step));

        unsigned long long vp = __ldcg(&g_aggr[tid * 2 + 0]);
        unsigned long long vn = __ldcg(&g_aggr[tid * 2 + 1]);
        double npd = (double)(vp >> 40);
        double nnd = (double)(vn >> 40);
        double spd = (double)(vp & ((1ull << 40) - 1)) * (1.0 / 65536.0) - npd;
        double snd = (double)(vn & ((1ull << 40) - 1)) * (1.0 / 65536.0) - nnd;
        s_np[tid] = (float)npd;  s_sp[tid] = (float)spd;
        s_nn[tid] = (float)nnd;  s_sn[tid] = (float)snd;
    }
    // posSize = sum of pos counts
    {
        float c = (tid < T_BINS) ? (float)(__ldcg(&g_aggr[tid * 2]) >> 40) : 0.f;
        red[tid] = c;
        __syncthreads();
#pragma unroll
        for (int s2 = 128; s2 > 0; s2 >>= 1) {
            if (tid < s2) red[tid] += red[tid + s2];
            __syncthreads();
        }
        if (tid == 0) {
            float cnt  = red[0];
            float Ptot = 0.5f * (float)N * (float)(N - 1);
            s_inv_pos = 1.0f / cnt;
            s_inv_neg = 1.0f / (Ptot - cnt);
        }
        __syncthreads();
    }

    if (tid < T_BINS) {
        float bp = s_c1[tid] * s_np[tid] - s_sp[tid] * inv_step;
        float bn = s_c1[tid] * s_nn[tid] - s_sn[tid] * inv_step;
        if (tid > 0 && s_al[tid - 1]) {
            bp += s_sp[tid - 1] * inv_step + s_c2[tid - 1] * s_np[tid - 1];
            bn += s_sn[tid - 1] * inv_step + s_c2[tid - 1] * s_nn[tid - 1];
        }
        hp[tid] = bp * s_inv_pos;
        hn[tid] = bn * s_inv_neg;
    }
    __syncthreads();

    // inclusive scan of hp (Hillis-Steele, 8 steps)
    for (int off = 1; off < T_BINS; off <<= 1) {
        float v = (tid < T_BINS && tid >= off) ? hp[tid - off] : 0.f;
        __syncthreads();
        if (tid < T_BINS) hp[tid] += v;
        __syncthreads();
    }

    // dot(hn, cdf) via power-of-2 tree reduce
    red[tid] = (tid < T_BINS) ? hn[tid] * hp[tid] : 0.f;
    __syncthreads();
#pragma unroll
    for (int s2 = 128; s2 > 0; s2 >>= 1) {
        if (tid < s2) red[tid] += red[tid + s2];
        __syncthreads();
    }
    if (tid == 0) out[0] = red[0];

    // Reset globals for the next replay (invariant: zero at kernel entry).
    for (int i = tid; i < 2 * T_BINS; i += 256) g_aggr[i] = 0ull;
    if (tid == 0) g_done = 0u;
}

extern "C" void kernel_launch(void* const* d_in, const int* in_sizes, int n_in,
                              void* d_out, int out_size)
{
    const float* feats = (const float*)d_in[0];
    const int*   cls   = (const int*)d_in[1];
    int N  = in_sizes[1];                 // classes element count = rows
    int NT = (N + TILE - 1) / TILE;
    int nblocks = NT * (NT + 1) / 2;      // 528 for N=1024

    size_t smem = (size_t)(2 * TILE * PADW) * sizeof(float)
                + (size_t)(2 * T_BINS * NREP) * sizeof(unsigned int)
                + (size_t)(2 * TILE + 4) * sizeof(int);
    cudaFuncSetAttribute(hist_loss_kernel,
                         cudaFuncAttributeMaxDynamicSharedMemorySize, (int)smem);

    hist_loss_kernel<<<nblocks, 256, smem>>>(feats, cls, (float*)d_out,
                                             N, NT, nblocks);
}